// round 10
// baseline (speedup 1.0000x reference)
#include <cuda_runtime.h>
#include <cuda_bf16.h>
#include <stdint.h>

#define BB 256
#define TT 128
#define II 256
#define HH 1024
#define CC 1000
#define NROUND 130
#define GPERS 96

typedef __nv_bfloat16 bf16;

// ---------------- device scratch (allocation-free) ----------------
__device__ float g_xp0[(size_t)BB * TT * HH];
__device__ float g_xp1[(size_t)BB * TT * HH];
__device__ bf16 g_xhi[(size_t)BB * TT * II];
__device__ bf16 g_xlo[(size_t)BB * TT * II];
__device__ bf16 g_h1hi[(size_t)BB * TT * HH];
__device__ bf16 g_h1lo[(size_t)BB * TT * HH];
__device__ bf16 g_h2hi[(size_t)BB * TT * HH];
__device__ bf16 g_h2lo[(size_t)BB * TT * HH];
__device__ bf16 g_Wih0hi[HH * II];  __device__ bf16 g_Wih0lo[HH * II];
__device__ bf16 g_Whh0hi[HH * HH];  __device__ bf16 g_Whh0lo[HH * HH];
__device__ bf16 g_Wih1hi[HH * HH];  __device__ bf16 g_Wih1lo[HH * HH];
__device__ bf16 g_Whh1hi[HH * HH];  __device__ bf16 g_Whh1lo[HH * HH];
__device__ bf16 g_fcWhi[HH * HH];   __device__ bf16 g_fcWlo[HH * HH];
__device__ int g_bar[256];

// ---------------- helpers ----------------
__device__ __forceinline__ uint32_t smem_u32(const void* p) {
    uint32_t a;
    asm("{ .reg .u64 t; cvta.to.shared.u64 t, %1; cvt.u32.u64 %0, t; }" : "=r"(a) : "l"(p));
    return a;
}
__device__ __forceinline__ void cp16(uint32_t dst, const void* src) {
    asm volatile("cp.async.cg.shared.global [%0], [%1], 16;" :: "r"(dst), "l"(src) : "memory");
}
#define CP_COMMIT() asm volatile("cp.async.commit_group;" ::: "memory")
#define CP_WAITG(n) asm volatile("cp.async.wait_group %0;" :: "n"(n) : "memory")

__device__ __forceinline__ void ldsm4(uint32_t* r, uint32_t addr) {
    asm volatile("ldmatrix.sync.aligned.m8n8.x4.shared.b16 {%0,%1,%2,%3}, [%4];"
        : "=r"(r[0]), "=r"(r[1]), "=r"(r[2]), "=r"(r[3]) : "r"(addr));
}
__device__ __forceinline__ void mma16816(float* c, const uint32_t* a, const uint32_t* b) {
    asm volatile(
        "mma.sync.aligned.m16n8k16.row.col.f32.bf16.bf16.f32 "
        "{%0,%1,%2,%3}, {%4,%5,%6,%7}, {%8,%9}, {%0,%1,%2,%3};"
        : "+f"(c[0]), "+f"(c[1]), "+f"(c[2]), "+f"(c[3])
        : "r"(a[0]), "r"(a[1]), "r"(a[2]), "r"(a[3]), "r"(b[0]), "r"(b[1]));
}
__device__ __forceinline__ float fast_tanh(float x) {
    float e = __expf(2.f * x);
    return 1.f - __fdividef(2.f, e + 1.f);
}
__device__ __forceinline__ void split2(float v, bf16& h, bf16& l) {
    h = __float2bfloat16(v);
    l = __float2bfloat16(v - __bfloat162float(h));
}

#define ROWB 144                         // 72 bf16 per smem row (64 + 8 pad)
#define SM_A_ST 9216                     // 64 rows * 144 B
#define SM_B_BASE 27648                  // 3 A-stages
#define SM_B_ST 18432                    // 128 rows * 144 B
#define SM_TOTAL 82944                   // 27648 + 3*18432

// ---------------- split kernels ----------------
__global__ void split_x_kernel(const float* __restrict__ s, int n) {
    int i = blockIdx.x * blockDim.x + threadIdx.x;
    if (i >= n) return;
    split2(s[i], g_xhi[i], g_xlo[i]);
}
__global__ void split_w0_kernel(const float* __restrict__ Wih0, const float* __restrict__ Whh0) {
    int i = blockIdx.x * blockDim.x + threadIdx.x;
    if (i < HH * II) split2(Wih0[i], g_Wih0hi[i], g_Wih0lo[i]);
    int j = i - HH * II;
    if (j >= 0 && j < HH * HH) split2(Whh0[j], g_Whh0hi[j], g_Whh0lo[j]);
}
__global__ void split_w1_kernel(const float* __restrict__ Wih1, const float* __restrict__ Whh1,
                                const float* __restrict__ fcW) {
    int i = blockIdx.x * blockDim.x + threadIdx.x;
    if (i < HH * HH) split2(Wih1[i], g_Wih1hi[i], g_Wih1lo[i]);
    int j = i - HH * HH;
    if (j >= 0 && j < HH * HH) split2(Whh1[j], g_Whh1hi[j], g_Whh1lo[j]);
    int k = i - 2 * HH * HH;
    if (k >= 0 && k < HH * HH) {
        int r = k >> 10, c = k & 1023;
        float v = (r < CC) ? fcW[r * HH + c] : 0.f;
        split2(v, g_fcWhi[k], g_fcWlo[k]);
    }
}
__global__ void zero_bar_kernel() {
    if (threadIdx.x < 256) g_bar[threadIdx.x] = 0;
}

// ---------------- shared mainloop: CTA 64(M) x 128(N), 128 threads ----------------
// warp tile 32x64: wm = wid&1 (M half), wn = wid>>1 (N half)
// acc[mt 0..1][j 0..7][4] ; 3-term split, K chunks of 64, 3-stage cp.async.
__device__ __forceinline__ void run_mainloop(
    float acc[2][8][4],
    const bf16* __restrict__ Ahi, const bf16* __restrict__ Alo,
    const bf16* __restrict__ Whi, const bf16* __restrict__ Wlo,
    size_t rowA0, size_t strideA, int K,
    uint32_t smem, int tid, int bm, int bn)
{
    const int lane = tid & 31, wid = tid >> 5;
    const int wm = wid & 1, wn = wid >> 1;
    const int CPT = K / 64, NC = 3 * CPT;

    auto load_chunk = [&](int c, int s) {
        int term = c / CPT;
        int kk = (c - term * CPT) * 64;
        const bf16* Ag = (term < 2) ? Ahi : Alo;
        const bf16* Wg = (term == 1) ? Wlo : Whi;
        uint32_t Ab = smem + s * SM_A_ST;
        uint32_t Bb = smem + SM_B_BASE + s * SM_B_ST;
        #pragma unroll
        for (int i = 0; i < 4; i++) {                 // A: 64 rows x 8 segs
            int task = tid + i * 128;
            int row = task >> 3, seg = task & 7;
            cp16(Ab + row * ROWB + seg * 16,
                 Ag + rowA0 + (size_t)(bm * 64 + row) * strideA + kk + seg * 8);
        }
        #pragma unroll
        for (int i = 0; i < 8; i++) {                 // B: 128 rows x 8 segs
            int task = tid + i * 128;
            int row = task >> 3, seg = task & 7;
            cp16(Bb + row * ROWB + seg * 16,
                 Wg + (size_t)(bn * 128 + row) * K + kk + seg * 8);
        }
        CP_COMMIT();
    };

    uint32_t aOff[2], bOff[4];
    #pragma unroll
    for (int mt = 0; mt < 2; mt++)
        aOff[mt] = (uint32_t)(wm * 32 + mt * 16 + (lane & 15)) * ROWB + ((lane >> 4) & 1) * 16;
    #pragma unroll
    for (int p = 0; p < 4; p++)
        bOff[p] = (uint32_t)(wn * 64 + p * 16 + ((lane >> 4) & 1) * 8 + (lane & 7)) * ROWB
                  + ((lane >> 3) & 1) * 16;

    load_chunk(0, 0);
    load_chunk(1, 1);
    int s = 0;
    for (int c = 0; c < NC; c++) {
        if (c + 1 < NC) { CP_WAITG(1); }              // chunk c resident, c+1 in flight
        else            { CP_WAITG(0); }              // FIX: last chunk must fully land
        __syncthreads();
        uint32_t Ab = smem + s * SM_A_ST;
        uint32_t Bb = smem + SM_B_BASE + s * SM_B_ST;
        #pragma unroll
        for (int k16 = 0; k16 < 4; k16++) {
            uint32_t a[2][4], b[4][4];
            ldsm4(a[0], Ab + aOff[0] + k16 * 32);
            ldsm4(a[1], Ab + aOff[1] + k16 * 32);
            #pragma unroll
            for (int p = 0; p < 4; p++) ldsm4(b[p], Bb + bOff[p] + k16 * 32);
            #pragma unroll
            for (int mt = 0; mt < 2; mt++)
                #pragma unroll
                for (int p = 0; p < 4; p++) {
                    mma16816(acc[mt][p * 2 + 0], a[mt], b[p]);
                    mma16816(acc[mt][p * 2 + 1], a[mt], b[p] + 2);
                }
        }
        __syncthreads();
        if (c + 2 < NC) load_chunk(c + 2, (c + 2) % 3);
        s++; if (s == 3) s = 0;
    }
}

// ---------------- generic GEMM (bulk proj EPI 0, FC EPI 2) ----------------
template <int EPI>
__global__ void __launch_bounds__(128) gemm_kernel(
    const bf16* __restrict__ Ahi, const bf16* __restrict__ Alo,
    size_t rowA0, size_t strideA, int K,
    const bf16* __restrict__ Bhi, const bf16* __restrict__ Blo,
    const float* __restrict__ e0, const float* __restrict__ e1,
    float* __restrict__ outF, size_t rowO0, size_t strideO)
{
    extern __shared__ __align__(16) char smem_raw[];
    uint32_t smem = smem_u32(smem_raw);
    const int tid = threadIdx.x;
    const int bn = blockIdx.x, bm = blockIdx.y;
    const int lane = tid & 31, wid = tid >> 5;
    const int wm = wid & 1, wn = wid >> 1;
    const int g = lane >> 2, tg = lane & 3;

    float acc[2][8][4];
    #pragma unroll
    for (int a = 0; a < 2; a++)
        #pragma unroll
        for (int b = 0; b < 8; b++)
            #pragma unroll
            for (int c = 0; c < 4; c++) acc[a][b][c] = 0.f;

    run_mainloop(acc, Ahi, Alo, Bhi, Blo, rowA0, strideA, K, smem, tid, bm, bn);

    #pragma unroll
    for (int mt = 0; mt < 2; mt++) {
        int r0 = bm * 64 + wm * 32 + mt * 16 + g;
        #pragma unroll
        for (int j = 0; j < 8; j++) {
            int n = bn * 128 + wn * 64 + j * 8 + tg * 2;
            if (EPI == 2 && n >= CC) continue;
            float b0 = (EPI == 0) ? (e0[n] + e1[n]) : e0[n];
            float b1 = (EPI == 0) ? (e0[n + 1] + e1[n + 1]) : e0[n + 1];
            float* p0 = outF + rowO0 + (size_t)r0 * strideO + n;
            float* p1 = outF + rowO0 + (size_t)(r0 + 8) * strideO + n;
            ((float2*)p0)[0] = make_float2(acc[mt][j][0] + b0, acc[mt][j][1] + b1);
            ((float2*)p1)[0] = make_float2(acc[mt][j][2] + b0, acc[mt][j][3] + b1);
        }
    }
}

// ---------------- persistent round kernel ----------------
// 96 CTAs: cta = z*32 + bm*8 + bn  (z phase, bm 0..3, bn 0..7)
//  z=0: h1[t] = tanh(xp0[t] + Whh0 @ h1[t-1])      t = r
//  z=1: xp1[t] = Wih1 @ h1[t] + bih1 + bhh1        t = r-1
//  z=2: h2[t] = tanh(xp1[t] + Whh1 @ h2[t-1])      t = r-2
// Grid barrier between rounds (monotonic per-round counters, zeroed per launch).
__global__ void __launch_bounds__(128) persistent_kernel(
    const float* __restrict__ bih1, const float* __restrict__ bhh1)
{
    extern __shared__ __align__(16) char smem_raw[];
    uint32_t smem = smem_u32(smem_raw);
    const int cta = blockIdx.x;
    const int z = cta >> 5;
    const int bm = (cta >> 3) & 3;
    const int bn = cta & 7;
    const int tid = threadIdx.x;
    const int lane = tid & 31, wid = tid >> 5;
    const int wm = wid & 1, wn = wid >> 1;
    const int g = lane >> 2, tg = lane & 3;
    const size_t TH = (size_t)TT * HH;

    for (int r = 0; r < NROUND; r++) {
        const int t = r - z;
        if (t >= 0 && t < TT) {
            float acc[2][8][4];
            #pragma unroll
            for (int a = 0; a < 2; a++)
                #pragma unroll
                for (int b = 0; b < 8; b++)
                    #pragma unroll
                    for (int c = 0; c < 4; c++) acc[a][b][c] = 0.f;

            const bf16 *Ahi, *Alo, *Whi, *Wlo;
            size_t rowA0 = 0;
            bool doGemm = true;
            if (z == 0) {
                Ahi = g_h1hi; Alo = g_h1lo; Whi = g_Whh0hi; Wlo = g_Whh0lo;
                rowA0 = (size_t)(t - 1) * HH; doGemm = (t > 0);
            } else if (z == 1) {
                Ahi = g_h1hi; Alo = g_h1lo; Whi = g_Wih1hi; Wlo = g_Wih1lo;
                rowA0 = (size_t)t * HH;
            } else {
                Ahi = g_h2hi; Alo = g_h2lo; Whi = g_Whh1hi; Wlo = g_Whh1lo;
                rowA0 = (size_t)(t - 1) * HH; doGemm = (t > 0);
            }
            if (doGemm)
                run_mainloop(acc, Ahi, Alo, Whi, Wlo, rowA0, TH, HH, smem, tid, bm, bn);

            const size_t rowT = (size_t)t * HH;
            #pragma unroll
            for (int mt = 0; mt < 2; mt++) {
                int r0 = bm * 64 + wm * 32 + mt * 16 + g;
                #pragma unroll
                for (int j = 0; j < 8; j++) {
                    int n = bn * 128 + wn * 64 + j * 8 + tg * 2;
                    if (z == 1) {
                        float b0 = bih1[n] + bhh1[n], b1 = bih1[n + 1] + bhh1[n + 1];
                        float* p0 = g_xp1 + rowT + (size_t)r0 * TH + n;
                        float* p1 = g_xp1 + rowT + (size_t)(r0 + 8) * TH + n;
                        ((float2*)p0)[0] = make_float2(acc[mt][j][0] + b0, acc[mt][j][1] + b1);
                        ((float2*)p1)[0] = make_float2(acc[mt][j][2] + b0, acc[mt][j][3] + b1);
                    } else {
                        const float* xps = (z == 0) ? g_xp0 : g_xp1;
                        bf16* oHi = (z == 0) ? g_h1hi : g_h2hi;
                        bf16* oLo = (z == 0) ? g_h1lo : g_h2lo;
                        #pragma unroll
                        for (int h = 0; h < 2; h++) {
                            int rr = r0 + h * 8;
                            const float2 xp2 = *(const float2*)(xps + rowT + (size_t)rr * TH + n);
                            float v0 = fast_tanh(acc[mt][j][h * 2 + 0] + xp2.x);
                            float v1 = fast_tanh(acc[mt][j][h * 2 + 1] + xp2.y);
                            bf16 h0, l0, h1v, l1;
                            split2(v0, h0, l0);
                            split2(v1, h1v, l1);
                            __nv_bfloat162 hp, lp;
                            hp.x = h0; hp.y = h1v;
                            lp.x = l0; lp.y = l1;
                            size_t go = rowT + (size_t)rr * TH + n;
                            *(__nv_bfloat162*)(oHi + go) = hp;
                            *(__nv_bfloat162*)(oLo + go) = lp;
                        }
                    }
                }
            }
        }

        // ---- grid barrier ----
        if (r + 1 < NROUND) {
            __threadfence();
            __syncthreads();
            if (tid == 0) {
                atomicAdd(&g_bar[r], 1);
                while (*(volatile int*)&g_bar[r] < GPERS) { }
            }
            __syncthreads();
        }
    }
}

// ---------------- host ----------------
extern "C" void kernel_launch(void* const* d_in, const int* in_sizes, int n_in,
                              void* d_out, int out_size)
{
    const float* x    = (const float*)d_in[0];
    const float* Wih0 = (const float*)d_in[1];
    const float* Whh0 = (const float*)d_in[2];
    const float* bih0 = (const float*)d_in[3];
    const float* bhh0 = (const float*)d_in[4];
    const float* Wih1 = (const float*)d_in[5];
    const float* Whh1 = (const float*)d_in[6];
    const float* bih1 = (const float*)d_in[7];
    const float* bhh1 = (const float*)d_in[8];
    const float* fcW  = (const float*)d_in[9];
    const float* fcb  = (const float*)d_in[10];
    float* out = (float*)d_out;

    void *p_xp0, *p_xhi, *p_xlo, *p_h2hi, *p_h2lo, *p_i0h, *p_i0l, *p_fch, *p_fcl;
    cudaGetSymbolAddress(&p_xp0, g_xp0);
    cudaGetSymbolAddress(&p_xhi, g_xhi);   cudaGetSymbolAddress(&p_xlo, g_xlo);
    cudaGetSymbolAddress(&p_h2hi, g_h2hi); cudaGetSymbolAddress(&p_h2lo, g_h2lo);
    cudaGetSymbolAddress(&p_i0h, g_Wih0hi); cudaGetSymbolAddress(&p_i0l, g_Wih0lo);
    cudaGetSymbolAddress(&p_fch, g_fcWhi);  cudaGetSymbolAddress(&p_fcl, g_fcWlo);

    static bool attr_done = false;
    if (!attr_done) {
        cudaFuncSetAttribute(gemm_kernel<0>, cudaFuncAttributeMaxDynamicSharedMemorySize, SM_TOTAL);
        cudaFuncSetAttribute(gemm_kernel<2>, cudaFuncAttributeMaxDynamicSharedMemorySize, SM_TOTAL);
        cudaFuncSetAttribute(persistent_kernel, cudaFuncAttributeMaxDynamicSharedMemorySize, SM_TOTAL);
        attr_done = true;
    }

    const size_t TH = (size_t)TT * HH;

    // 1-3. fp32 -> bf16 hi/lo splits (3 launches)
    split_x_kernel<<<(BB * TT * II + 255) / 256, 256>>>(x, BB * TT * II);
    split_w0_kernel<<<(HH * II + HH * HH + 255) / 256, 256>>>(Wih0, Whh0);
    split_w1_kernel<<<(3 * HH * HH + 255) / 256, 256>>>(Wih1, Whh1, fcW);

    // 4. zero barrier counters (replay-safe)
    zero_bar_kernel<<<1, 256>>>();

    // 5. layer0 bulk input projection: xp0 = x @ Wih0^T + bih0 + bhh0
    gemm_kernel<0><<<dim3(HH / 128, (BB * TT) / 64), 128, SM_TOTAL>>>(
        (bf16*)p_xhi, (bf16*)p_xlo, 0, II, II,
        (bf16*)p_i0h, (bf16*)p_i0l, bih0, bhh0,
        (float*)p_xp0, 0, HH);

    // 6. persistent pipelined rounds
    persistent_kernel<<<GPERS, 128, SM_TOTAL>>>(bih1, bhh1);

    // 7. FC on h2[:, T-1, :]
    gemm_kernel<2><<<dim3(HH / 128, BB / 64), 128, SM_TOTAL>>>(
        (bf16*)p_h2hi, (bf16*)p_h2lo, (size_t)(TT - 1) * HH, TH, HH,
        (bf16*)p_fch, (bf16*)p_fcl, fcb, nullptr,
        out, 0, CC);
}

// round 12
// speedup vs baseline: 1.8406x; 1.8406x over previous
#include <cuda_runtime.h>
#include <cuda_fp16.h>
#include <stdint.h>

#define BB 256
#define TT 128
#define II 256
#define HH 1024
#define CC 1000

typedef __half hf;

// ---------------- device scratch (allocation-free) ----------------
__device__ float g_xp0[(size_t)BB * TT * HH];
__device__ float g_xp1[(size_t)BB * TT * HH];
__device__ hf g_xh[(size_t)BB * TT * II];        // x in fp16
__device__ hf g_h1[(size_t)BB * TT * HH];        // layer-1 hidden, fp16
__device__ hf g_h2[(size_t)BB * TT * HH];        // layer-2 hidden, fp16
__device__ hf g_Wih0hi[HH * II];  __device__ hf g_Wih0lo[HH * II];
__device__ hf g_Whh0hi[HH * HH];  __device__ hf g_Whh0lo[HH * HH];
__device__ hf g_Wih1hi[HH * HH];  __device__ hf g_Wih1lo[HH * HH];
__device__ hf g_Whh1hi[HH * HH];  __device__ hf g_Whh1lo[HH * HH];
__device__ hf g_fcWhi[HH * HH];   __device__ hf g_fcWlo[HH * HH];   // padded to 1024 rows

// ---------------- helpers ----------------
__device__ __forceinline__ uint32_t smem_u32(const void* p) {
    uint32_t a;
    asm("{ .reg .u64 t; cvta.to.shared.u64 t, %1; cvt.u32.u64 %0, t; }" : "=r"(a) : "l"(p));
    return a;
}
__device__ __forceinline__ void cp16(uint32_t dst, const void* src) {
    asm volatile("cp.async.cg.shared.global [%0], [%1], 16;" :: "r"(dst), "l"(src) : "memory");
}
#define CP_COMMIT() asm volatile("cp.async.commit_group;" ::: "memory")
#define CP_WAITG(n) asm volatile("cp.async.wait_group %0;" :: "n"(n) : "memory")

__device__ __forceinline__ void ldsm4(uint32_t* r, uint32_t addr) {
    asm volatile("ldmatrix.sync.aligned.m8n8.x4.shared.b16 {%0,%1,%2,%3}, [%4];"
        : "=r"(r[0]), "=r"(r[1]), "=r"(r[2]), "=r"(r[3]) : "r"(addr));
}
__device__ __forceinline__ void mma16816(float* c, const uint32_t* a, const uint32_t* b) {
    asm volatile(
        "mma.sync.aligned.m16n8k16.row.col.f32.f16.f16.f32 "
        "{%0,%1,%2,%3}, {%4,%5,%6,%7}, {%8,%9}, {%0,%1,%2,%3};"
        : "+f"(c[0]), "+f"(c[1]), "+f"(c[2]), "+f"(c[3])
        : "r"(a[0]), "r"(a[1]), "r"(a[2]), "r"(a[3]), "r"(b[0]), "r"(b[1]));
}
__device__ __forceinline__ float fast_tanh(float x) {
    float e = __expf(2.f * x);
    return 1.f - __fdividef(2.f, e + 1.f);
}

#define PAD_STRIDE 72                      // hf per smem row (64 + 8 pad) = 144 B
#define ROWB (PAD_STRIDE * 2)

// ---------------- split kernels ----------------
// weights: fp32 -> fp16 hi + lo (lo = residual)
__global__ void splitw_kernel(const float* __restrict__ s, hf* __restrict__ hi,
                              hf* __restrict__ lo, int n) {
    int i = blockIdx.x * blockDim.x + threadIdx.x;
    if (i >= n) return;
    float v = s[i];
    hf h = __float2half(v);
    hi[i] = h;
    lo[i] = __float2half(v - __half2float(h));
}
// x: fp32 -> fp16 single
__global__ void cvt_kernel(const float* __restrict__ s, hf* __restrict__ d, int n) {
    int i = blockIdx.x * blockDim.x + threadIdx.x;
    if (i < n) d[i] = __float2half(s[i]);
}
__global__ void split_pad_fc(const float* __restrict__ s, hf* __restrict__ hi,
                             hf* __restrict__ lo) {
    int i = blockIdx.x * blockDim.x + threadIdx.x;
    if (i >= HH * HH) return;
    int r = i >> 10, c = i & 1023;
    float v = (r < CC) ? s[r * HH + c] : 0.f;
    hf h = __float2half(v);
    hi[i] = h;
    lo[i] = __float2half(v - __half2float(h));
}

// ---------------- shared mainloop (2-unit fp16 split, 3-stage cp.async + ldmatrix) ----------------
// acc += A @ (Whi + Wlo)^T for a 32x64 CTA tile. A is single fp16.
struct MLArgs {
    const hf *A, *Whi, *Wlo;
    size_t rowA0, strideA;
    int K;          // K per term (multiple of 64)
};

__device__ __forceinline__ void run_mainloop_impl(
    float acc[4][4], const MLArgs& ml,
    hf* sA, hf* sB,            // [3][32*PAD_STRIDE], [3][64*PAD_STRIDE]
    int tid, int bm, int bn)
{
    const int lane = tid & 31;
    const int wid = tid >> 5;
    const int wm = wid & 1, wn = wid >> 1;

    const uint32_t sAu = smem_u32(sA);
    const uint32_t sBu = smem_u32(sB);

    const int CPT = ml.K / 64;
    const int NC = 2 * CPT;

    auto load_chunk = [&](int c, int s) {
        int term = c / CPT;
        int kk = (c - term * CPT) * 64;
        const hf* Wg = term ? ml.Wlo : ml.Whi;
        uint32_t Ab = sAu + s * (32 * ROWB);
        uint32_t Bb = sBu + s * (64 * ROWB);
        #pragma unroll
        for (int i = 0; i < 2; i++) {               // A: 32 rows x 8 segs
            int task = tid + i * 128;
            int row = task >> 3, seg = task & 7;
            const hf* src = ml.A + ml.rowA0 + (size_t)(bm * 32 + row) * ml.strideA + kk + seg * 8;
            cp16(Ab + row * ROWB + seg * 16, src);
        }
        #pragma unroll
        for (int i = 0; i < 4; i++) {               // B: 64 rows x 8 segs
            int task = tid + i * 128;
            int row = task >> 3, seg = task & 7;
            const hf* src = Wg + (size_t)(bn * 64 + row) * ml.K + kk + seg * 8;
            cp16(Bb + row * ROWB + seg * 16, src);
        }
        CP_COMMIT();
    };

    const uint32_t aOff = (uint32_t)(wm * 16 + (lane & 15)) * ROWB + ((lane >> 4) & 1) * 16;
    const uint32_t bRow = (uint32_t)(wn * 32 + ((lane >> 4) & 1) * 8 + (lane & 7));
    const uint32_t bOff = bRow * ROWB + ((lane >> 3) & 1) * 16;

    load_chunk(0, 0);
    load_chunk(1, 1);
    for (int c = 0; c < NC; c++) {
        int s = c - (c / 3) * 3;                    // c % 3
        if (c + 1 < NC) { CP_WAITG(1); }            // chunk c resident
        else            { CP_WAITG(0); }            // last chunk: full drain
        __syncthreads();
        uint32_t Ab = sAu + s * (32 * ROWB) + aOff;
        uint32_t Bb = sBu + s * (64 * ROWB) + bOff;
        #pragma unroll
        for (int k16 = 0; k16 < 4; k16++) {
            uint32_t a[4], b01[4], b23[4];
            ldsm4(a, Ab + k16 * 32);
            ldsm4(b01, Bb + k16 * 32);              // nt 0,1
            ldsm4(b23, Bb + 16 * ROWB + k16 * 32);  // nt 2,3
            mma16816(acc[0], a, b01);
            mma16816(acc[1], a, b01 + 2);
            mma16816(acc[2], a, b23);
            mma16816(acc[3], a, b23 + 2);
        }
        __syncthreads();
        if (c + 2 < NC) load_chunk(c + 2, (c + 2) - ((c + 2) / 3) * 3);
    }
}

// ---------------- generic GEMM (bulk proj EPI 0, FC EPI 2) ----------------
template <int EPI>
__global__ void __launch_bounds__(128) gemm_kernel(
    const hf* __restrict__ A, size_t rowA0, size_t strideA, int K,
    const hf* __restrict__ Whi, const hf* __restrict__ Wlo,
    const float* __restrict__ e0, const float* __restrict__ e1,
    float* __restrict__ outF, size_t rowO0, size_t strideO)
{
    __shared__ __align__(16) hf sA[3][32 * PAD_STRIDE];
    __shared__ __align__(16) hf sB[3][64 * PAD_STRIDE];

    const int tid = threadIdx.x;
    const int bn = blockIdx.x, bm = blockIdx.y;
    const int wid = tid >> 5, lane = tid & 31;
    const int g = lane >> 2, tg = lane & 3;
    const int wm = wid & 1, wn = wid >> 1;

    float acc[4][4];
    #pragma unroll
    for (int i = 0; i < 4; i++)
        #pragma unroll
        for (int j = 0; j < 4; j++) acc[i][j] = 0.f;

    MLArgs ml{A, Whi, Wlo, rowA0, strideA, K};
    run_mainloop_impl(acc, ml, &sA[0][0], &sB[0][0], tid, bm, bn);

    const int r0 = bm * 32 + wm * 16 + g;
    #pragma unroll
    for (int nt = 0; nt < 4; nt++) {
        int n = bn * 64 + wn * 32 + nt * 8 + tg * 2;
        if (EPI == 2 && n >= CC) continue;
        float b0 = (EPI == 0) ? (e0[n] + e1[n]) : e0[n];
        float b1 = (EPI == 0) ? (e0[n + 1] + e1[n + 1]) : e0[n + 1];
        float* p0 = outF + rowO0 + (size_t)r0 * strideO + n;
        float* p1 = outF + rowO0 + (size_t)(r0 + 8) * strideO + n;
        ((float2*)p0)[0] = make_float2(acc[nt][0] + b0, acc[nt][1] + b1);
        ((float2*)p1)[0] = make_float2(acc[nt][2] + b0, acc[nt][3] + b1);
    }
}

// ---------------- pipelined round kernel ----------------
// Phase z = blockIdx.z, t = r - z:
//  z=0: h1[t] = tanh(xp0[t] + Whh0 @ h1[t-1])
//  z=1: xp1[t] = Wih1 @ h1[t] + bih1 + bhh1
//  z=2: h2[t] = tanh(xp1[t] + Whh1 @ h2[t-1])
__global__ void __launch_bounds__(128) round_kernel(
    int r, const float* __restrict__ bih1, const float* __restrict__ bhh1)
{
    const int z = blockIdx.z;
    const int t = r - z;
    if (t < 0 || t >= TT) return;

    const size_t TH = (size_t)TT * HH;
    MLArgs ml;
    ml.strideA = TH;  ml.K = HH;
    bool doGemm = true;
    if (z == 0) {
        ml.A = g_h1; ml.Whi = g_Whh0hi; ml.Wlo = g_Whh0lo;
        ml.rowA0 = (size_t)(t - 1) * HH;  doGemm = (t > 0);
    } else if (z == 1) {
        ml.A = g_h1; ml.Whi = g_Wih1hi; ml.Wlo = g_Wih1lo;
        ml.rowA0 = (size_t)t * HH;
    } else {
        ml.A = g_h2; ml.Whi = g_Whh1hi; ml.Wlo = g_Whh1lo;
        ml.rowA0 = (size_t)(t - 1) * HH;  doGemm = (t > 0);
    }

    __shared__ __align__(16) hf sA[3][32 * PAD_STRIDE];
    __shared__ __align__(16) hf sB[3][64 * PAD_STRIDE];

    const int tid = threadIdx.x;
    const int bn = blockIdx.x, bm = blockIdx.y;
    const int wid = tid >> 5, lane = tid & 31;
    const int g = lane >> 2, tg = lane & 3;
    const int wm = wid & 1, wn = wid >> 1;

    float acc[4][4];
    #pragma unroll
    for (int i = 0; i < 4; i++)
        #pragma unroll
        for (int j = 0; j < 4; j++) acc[i][j] = 0.f;

    if (doGemm)
        run_mainloop_impl(acc, ml, &sA[0][0], &sB[0][0], tid, bm, bn);

    // ---------------- epilogue ----------------
    const int r0 = bm * 32 + wm * 16 + g;
    const size_t rowT = (size_t)t * HH;
    const size_t TH2 = (size_t)TT * HH;

    #pragma unroll
    for (int nt = 0; nt < 4; nt++) {
        int n = bn * 64 + wn * 32 + nt * 8 + tg * 2;
        if (z == 1) {
            float b0 = bih1[n] + bhh1[n], b1 = bih1[n + 1] + bhh1[n + 1];
            float* p0 = g_xp1 + rowT + (size_t)r0 * TH2 + n;
            float* p1 = g_xp1 + rowT + (size_t)(r0 + 8) * TH2 + n;
            ((float2*)p0)[0] = make_float2(acc[nt][0] + b0, acc[nt][1] + b1);
            ((float2*)p1)[0] = make_float2(acc[nt][2] + b0, acc[nt][3] + b1);
        } else {
            const float* xps = (z == 0) ? g_xp0 : g_xp1;
            hf* oH = (z == 0) ? g_h1 : g_h2;
            #pragma unroll
            for (int h = 0; h < 2; h++) {
                int rr = r0 + h * 8;
                const float2 xp2 = *(const float2*)(xps + rowT + (size_t)rr * TH2 + n);
                float v0 = fast_tanh(acc[nt][h * 2 + 0] + xp2.x);
                float v1 = fast_tanh(acc[nt][h * 2 + 1] + xp2.y);
                __half2 hp;
                hp.x = __float2half(v0);
                hp.y = __float2half(v1);
                *(__half2*)(oH + rowT + (size_t)rr * TH2 + n) = hp;
            }
        }
    }
}

// ---------------- host ----------------
extern "C" void kernel_launch(void* const* d_in, const int* in_sizes, int n_in,
                              void* d_out, int out_size)
{
    const float* x    = (const float*)d_in[0];
    const float* Wih0 = (const float*)d_in[1];
    const float* Whh0 = (const float*)d_in[2];
    const float* bih0 = (const float*)d_in[3];
    const float* bhh0 = (const float*)d_in[4];
    const float* Wih1 = (const float*)d_in[5];
    const float* Whh1 = (const float*)d_in[6];
    const float* bih1 = (const float*)d_in[7];
    const float* bhh1 = (const float*)d_in[8];
    const float* fcW  = (const float*)d_in[9];
    const float* fcb  = (const float*)d_in[10];
    float* out = (float*)d_out;

    void *p_xp0, *p_xh, *p_h2, *p_i0h, *p_i0l, *p_r0h, *p_r0l;
    void *p_i1h, *p_i1l, *p_r1h, *p_r1l, *p_fch, *p_fcl;
    cudaGetSymbolAddress(&p_xp0, g_xp0);
    cudaGetSymbolAddress(&p_xh, g_xh);
    cudaGetSymbolAddress(&p_h2, g_h2);
    cudaGetSymbolAddress(&p_i0h, g_Wih0hi); cudaGetSymbolAddress(&p_i0l, g_Wih0lo);
    cudaGetSymbolAddress(&p_r0h, g_Whh0hi); cudaGetSymbolAddress(&p_r0l, g_Whh0lo);
    cudaGetSymbolAddress(&p_i1h, g_Wih1hi); cudaGetSymbolAddress(&p_i1l, g_Wih1lo);
    cudaGetSymbolAddress(&p_r1h, g_Whh1hi); cudaGetSymbolAddress(&p_r1l, g_Whh1lo);
    cudaGetSymbolAddress(&p_fch, g_fcWhi);  cudaGetSymbolAddress(&p_fcl, g_fcWlo);

    // 1. conversions / splits
    cvt_kernel<<<(BB * TT * II + 255) / 256, 256>>>(x, (hf*)p_xh, BB * TT * II);
    splitw_kernel<<<(HH * II + 255) / 256, 256>>>(Wih0, (hf*)p_i0h, (hf*)p_i0l, HH * II);
    splitw_kernel<<<(HH * HH + 255) / 256, 256>>>(Whh0, (hf*)p_r0h, (hf*)p_r0l, HH * HH);
    splitw_kernel<<<(HH * HH + 255) / 256, 256>>>(Wih1, (hf*)p_i1h, (hf*)p_i1l, HH * HH);
    splitw_kernel<<<(HH * HH + 255) / 256, 256>>>(Whh1, (hf*)p_r1h, (hf*)p_r1l, HH * HH);
    split_pad_fc<<<(HH * HH + 255) / 256, 256>>>(fcW, (hf*)p_fch, (hf*)p_fcl);

    const size_t TH = (size_t)TT * HH;
    const dim3 projGrid(HH / 64, (BB * TT) / 32);   // (16, 1024)
    const dim3 roundGrid(HH / 64, BB / 32, 3);      // (16, 8, 3) = 384 CTAs
    const dim3 fcGrid(HH / 64, BB / 32);            // (16, 8)

    // 2. layer0 bulk input projection: xp0 = x @ Wih0^T + bih0 + bhh0
    gemm_kernel<0><<<projGrid, 128>>>(
        (hf*)p_xh, 0, II, II,
        (hf*)p_i0h, (hf*)p_i0l, bih0, bhh0,
        (float*)p_xp0, 0, HH);

    // 3. pipelined rounds: layer0 step | layer1 proj | layer1 step
    for (int r = 0; r <= TT + 1; r++)
        round_kernel<<<roundGrid, 128>>>(r, bih1, bhh1);

    // 4. FC on h2[:, T-1, :]
    gemm_kernel<2><<<fcGrid, 128>>>(
        (hf*)p_h2, (size_t)(TT - 1) * HH, TH, HH,
        (hf*)p_fch, (hf*)p_fcl, fcb, nullptr,
        out, 0, CC);
}

// round 13
// speedup vs baseline: 1.9200x; 1.0431x over previous
#include <cuda_runtime.h>
#include <cuda_fp16.h>
#include <stdint.h>

#define BB 256
#define TT 128
#define II 256
#define HH 1024
#define CC 1000

typedef __half hf;

// ---------------- device scratch (allocation-free) ----------------
__device__ float g_xp0[(size_t)BB * TT * HH];
__device__ float g_xp1[(size_t)BB * TT * HH];
__device__ hf g_xh[(size_t)BB * TT * II];
__device__ hf g_h1[(size_t)BB * TT * HH];
__device__ hf g_h2[(size_t)BB * TT * HH];
__device__ hf g_Wih0hi[HH * II];  __device__ hf g_Wih0lo[HH * II];
__device__ hf g_Whh0hi[HH * HH];  __device__ hf g_Whh0lo[HH * HH];
__device__ hf g_Wih1hi[HH * HH];  __device__ hf g_Wih1lo[HH * HH];
__device__ hf g_Whh1hi[HH * HH];  __device__ hf g_Whh1lo[HH * HH];
__device__ hf g_fcWhi[HH * HH];   __device__ hf g_fcWlo[HH * HH];

// ---------------- helpers ----------------
__device__ __forceinline__ uint32_t smem_u32(const void* p) {
    uint32_t a;
    asm("{ .reg .u64 t; cvta.to.shared.u64 t, %1; cvt.u32.u64 %0, t; }" : "=r"(a) : "l"(p));
    return a;
}
__device__ __forceinline__ void cp16(uint32_t dst, const void* src) {
    asm volatile("cp.async.cg.shared.global [%0], [%1], 16;" :: "r"(dst), "l"(src) : "memory");
}
#define CP_COMMIT() asm volatile("cp.async.commit_group;" ::: "memory")
#define CP_WAITG(n) asm volatile("cp.async.wait_group %0;" :: "n"(n) : "memory")

__device__ __forceinline__ void ldsm4(uint32_t* r, uint32_t addr) {
    asm volatile("ldmatrix.sync.aligned.m8n8.x4.shared.b16 {%0,%1,%2,%3}, [%4];"
        : "=r"(r[0]), "=r"(r[1]), "=r"(r[2]), "=r"(r[3]) : "r"(addr));
}
__device__ __forceinline__ void mma16816(float* c, const uint32_t* a, const uint32_t* b) {
    asm volatile(
        "mma.sync.aligned.m16n8k16.row.col.f32.f16.f16.f32 "
        "{%0,%1,%2,%3}, {%4,%5,%6,%7}, {%8,%9}, {%0,%1,%2,%3};"
        : "+f"(c[0]), "+f"(c[1]), "+f"(c[2]), "+f"(c[3])
        : "r"(a[0]), "r"(a[1]), "r"(a[2]), "r"(a[3]), "r"(b[0]), "r"(b[1]));
}
__device__ __forceinline__ float fast_tanh(float x) {
    float e = __expf(2.f * x);
    return 1.f - __fdividef(2.f, e + 1.f);
}

// smem layout (dynamic): 3 stages of [A 32x72hf | Bhi 64x72hf | Blo 64x72hf]
#define ROWB 144
#define ASTG 4608            // 32*144
#define BSTG 9216            // 64*144
#define STG  23040           // ASTG + 2*BSTG
#define SMEM_DYN (3 * STG)   // 69120

// ---------------- split kernels ----------------
__global__ void splitw_kernel(const float* __restrict__ s, hf* __restrict__ hi,
                              hf* __restrict__ lo, int n) {
    int i = blockIdx.x * blockDim.x + threadIdx.x;
    if (i >= n) return;
    float v = s[i];
    hf h = __float2half(v);
    hi[i] = h;
    lo[i] = __float2half(v - __half2float(h));
}
__global__ void cvt_kernel(const float* __restrict__ s, hf* __restrict__ d, int n) {
    int i = blockIdx.x * blockDim.x + threadIdx.x;
    if (i < n) d[i] = __float2half(s[i]);
}
__global__ void split_pad_fc(const float* __restrict__ s, hf* __restrict__ hi,
                             hf* __restrict__ lo) {
    int i = blockIdx.x * blockDim.x + threadIdx.x;
    if (i >= HH * HH) return;
    int r = i >> 10, c = i & 1023;
    float v = (r < CC) ? s[r * HH + c] : 0.f;
    hf h = __float2half(v);
    hi[i] = h;
    lo[i] = __float2half(v - __half2float(h));
}

// ---------------- fused-term mainloop ----------------
// 256 threads. warp-group wg (wid>>2): 0 -> A@Whi, 1 -> A@Wlo.
// Within group: wq = wid&3, wm = wq&1, wn = wq>>1 (16x32 warp tile of 32x64 CTA tile).
// Single pass over K (NC = K/64 chunks); both B terms staged per chunk.
__device__ __forceinline__ void run_ml(
    float acc[4][4],
    const hf* __restrict__ A, const hf* __restrict__ Whi, const hf* __restrict__ Wlo,
    size_t rowA0, size_t strideA, int K,
    uint32_t sm, int tid, int bm, int bn, int wg, int wq)
{
    const int lane = tid & 31;
    const int wm = wq & 1, wn = wq >> 1;
    const int NC = K / 64;

    auto load_chunk = [&](int c, int s) {
        int kk = c * 64;
        uint32_t st = sm + s * STG;
        {   // A: 32 rows x 8 segs = 256 tasks, 1/thread
            int row = tid >> 3, seg = tid & 7;
            cp16(st + row * ROWB + seg * 16,
                 A + rowA0 + (size_t)(bm * 32 + row) * strideA + kk + seg * 8);
        }
        #pragma unroll
        for (int i = 0; i < 2; i++) {   // Bhi + Blo: 64 rows x 8 segs each
            int task = tid + i * 256;
            int row = task >> 3, seg = task & 7;
            size_t go = (size_t)(bn * 64 + row) * K + kk + seg * 8;
            cp16(st + ASTG + row * ROWB + seg * 16, Whi + go);
            cp16(st + ASTG + BSTG + row * ROWB + seg * 16, Wlo + go);
        }
        CP_COMMIT();
    };

    const uint32_t aOff = (uint32_t)(wm * 16 + (lane & 15)) * ROWB + ((lane >> 4) & 1) * 16;
    const uint32_t bOff = (uint32_t)(wn * 32 + ((lane >> 4) & 1) * 8 + (lane & 7)) * ROWB
                          + ((lane >> 3) & 1) * 16;
    const uint32_t bBase = ASTG + (uint32_t)wg * BSTG;

    load_chunk(0, 0);
    load_chunk(1, 1);
    for (int c = 0; c < NC; c++) {
        int s = c - (c / 3) * 3;
        if (c + 1 < NC) { CP_WAITG(1); }
        else            { CP_WAITG(0); }
        __syncthreads();
        uint32_t Ab = sm + s * STG + aOff;
        uint32_t Bb = sm + s * STG + bBase + bOff;
        #pragma unroll
        for (int k16 = 0; k16 < 4; k16++) {
            uint32_t a[4], b01[4], b23[4];
            ldsm4(a, Ab + k16 * 32);
            ldsm4(b01, Bb + k16 * 32);
            ldsm4(b23, Bb + 16 * ROWB + k16 * 32);
            mma16816(acc[0], a, b01);
            mma16816(acc[1], a, b01 + 2);
            mma16816(acc[2], a, b23);
            mma16816(acc[3], a, b23 + 2);
        }
        __syncthreads();
        if (c + 2 < NC) load_chunk(c + 2, (c + 2) - ((c + 2) / 3) * 3);
    }
}

// ---------------- generic GEMM (bulk proj EPI 0, FC EPI 2) ----------------
template <int EPI>
__global__ void __launch_bounds__(256) gemm_kernel(
    const hf* __restrict__ A, size_t rowA0, size_t strideA, int K,
    const hf* __restrict__ Whi, const hf* __restrict__ Wlo,
    const float* __restrict__ e0, const float* __restrict__ e1,
    float* __restrict__ outF, size_t rowO0, size_t strideO)
{
    extern __shared__ __align__(16) char smem_raw[];
    uint32_t sm = smem_u32(smem_raw);
    const int tid = threadIdx.x;
    const int bn = blockIdx.x, bm = blockIdx.y;
    const int lane = tid & 31, wid = tid >> 5;
    const int wg = wid >> 2, wq = wid & 3;
    const int wm = wq & 1, wn = wq >> 1;
    const int g = lane >> 2, tg = lane & 3;

    float acc[4][4];
    #pragma unroll
    for (int i = 0; i < 4; i++)
        #pragma unroll
        for (int j = 0; j < 4; j++) acc[i][j] = 0.f;

    run_ml(acc, A, Whi, Wlo, rowA0, strideA, K, sm, tid, bm, bn, wg, wq);

    // cross-group reduction: lo group -> smem, hi group adds
    float* red = (float*)smem_raw;
    if (wg == 1) {
        #pragma unroll
        for (int nt = 0; nt < 4; nt++)
            #pragma unroll
            for (int j = 0; j < 4; j++) red[(tid - 128) * 16 + nt * 4 + j] = acc[nt][j];
    }
    __syncthreads();
    if (wg == 0) {
        #pragma unroll
        for (int nt = 0; nt < 4; nt++)
            #pragma unroll
            for (int j = 0; j < 4; j++) acc[nt][j] += red[tid * 16 + nt * 4 + j];

        const int r0 = bm * 32 + wm * 16 + g;
        #pragma unroll
        for (int nt = 0; nt < 4; nt++) {
            int n = bn * 64 + wn * 32 + nt * 8 + tg * 2;
            if (EPI == 2 && n >= CC) continue;
            float b0 = (EPI == 0) ? (e0[n] + e1[n]) : e0[n];
            float b1 = (EPI == 0) ? (e0[n + 1] + e1[n + 1]) : e0[n + 1];
            float* p0 = outF + rowO0 + (size_t)r0 * strideO + n;
            float* p1 = outF + rowO0 + (size_t)(r0 + 8) * strideO + n;
            ((float2*)p0)[0] = make_float2(acc[nt][0] + b0, acc[nt][1] + b1);
            ((float2*)p1)[0] = make_float2(acc[nt][2] + b0, acc[nt][3] + b1);
        }
    }
}

// ---------------- pipelined round kernel ----------------
// Phase z = blockIdx.z, t = r - z:
//  z=0: h1[t] = tanh(xp0[t] + Whh0 @ h1[t-1])
//  z=1: xp1[t] = Wih1 @ h1[t] + bih1 + bhh1
//  z=2: h2[t] = tanh(xp1[t] + Whh1 @ h2[t-1])
__global__ void __launch_bounds__(256) round_kernel(
    int r, const float* __restrict__ bih1, const float* __restrict__ bhh1)
{
    const int z = blockIdx.z;
    const int t = r - z;
    if (t < 0 || t >= TT) return;

    extern __shared__ __align__(16) char smem_raw[];
    uint32_t sm = smem_u32(smem_raw);
    const size_t TH = (size_t)TT * HH;

    const hf *A, *Whi, *Wlo;
    size_t rowA0 = 0;
    bool doGemm = true;
    if (z == 0) {
        A = g_h1; Whi = g_Whh0hi; Wlo = g_Whh0lo;
        rowA0 = (size_t)(t - 1) * HH;  doGemm = (t > 0);
    } else if (z == 1) {
        A = g_h1; Whi = g_Wih1hi; Wlo = g_Wih1lo;
        rowA0 = (size_t)t * HH;
    } else {
        A = g_h2; Whi = g_Whh1hi; Wlo = g_Whh1lo;
        rowA0 = (size_t)(t - 1) * HH;  doGemm = (t > 0);
    }

    const int tid = threadIdx.x;
    const int bn = blockIdx.x, bm = blockIdx.y;
    const int lane = tid & 31, wid = tid >> 5;
    const int wg = wid >> 2, wq = wid & 3;
    const int wm = wq & 1, wn = wq >> 1;
    const int g = lane >> 2, tg = lane & 3;

    float acc[4][4];
    #pragma unroll
    for (int i = 0; i < 4; i++)
        #pragma unroll
        for (int j = 0; j < 4; j++) acc[i][j] = 0.f;

    if (doGemm)
        run_ml(acc, A, Whi, Wlo, rowA0, TH, HH, sm, tid, bm, bn, wg, wq);

    // cross-group reduction
    float* red = (float*)smem_raw;
    if (wg == 1) {
        #pragma unroll
        for (int nt = 0; nt < 4; nt++)
            #pragma unroll
            for (int j = 0; j < 4; j++) red[(tid - 128) * 16 + nt * 4 + j] = acc[nt][j];
    }
    __syncthreads();
    if (wg == 0) {
        #pragma unroll
        for (int nt = 0; nt < 4; nt++)
            #pragma unroll
            for (int j = 0; j < 4; j++) acc[nt][j] += red[tid * 16 + nt * 4 + j];

        const int r0 = bm * 32 + wm * 16 + g;
        const size_t rowT = (size_t)t * HH;
        #pragma unroll
        for (int nt = 0; nt < 4; nt++) {
            int n = bn * 64 + wn * 32 + nt * 8 + tg * 2;
            if (z == 1) {
                float b0 = bih1[n] + bhh1[n], b1 = bih1[n + 1] + bhh1[n + 1];
                float* p0 = g_xp1 + rowT + (size_t)r0 * TH + n;
                float* p1 = g_xp1 + rowT + (size_t)(r0 + 8) * TH + n;
                ((float2*)p0)[0] = make_float2(acc[nt][0] + b0, acc[nt][1] + b1);
                ((float2*)p1)[0] = make_float2(acc[nt][2] + b0, acc[nt][3] + b1);
            } else {
                const float* xps = (z == 0) ? g_xp0 : g_xp1;
                hf* oH = (z == 0) ? g_h1 : g_h2;
                #pragma unroll
                for (int h = 0; h < 2; h++) {
                    int rr = r0 + h * 8;
                    const float2 xp2 = *(const float2*)(xps + rowT + (size_t)rr * TH + n);
                    float v0 = fast_tanh(acc[nt][h * 2 + 0] + xp2.x);
                    float v1 = fast_tanh(acc[nt][h * 2 + 1] + xp2.y);
                    __half2 hp;
                    hp.x = __float2half(v0);
                    hp.y = __float2half(v1);
                    *(__half2*)(oH + rowT + (size_t)rr * TH + n) = hp;
                }
            }
        }
    }
}

// ---------------- host ----------------
extern "C" void kernel_launch(void* const* d_in, const int* in_sizes, int n_in,
                              void* d_out, int out_size)
{
    const float* x    = (const float*)d_in[0];
    const float* Wih0 = (const float*)d_in[1];
    const float* Whh0 = (const float*)d_in[2];
    const float* bih0 = (const float*)d_in[3];
    const float* bhh0 = (const float*)d_in[4];
    const float* Wih1 = (const float*)d_in[5];
    const float* Whh1 = (const float*)d_in[6];
    const float* bih1 = (const float*)d_in[7];
    const float* bhh1 = (const float*)d_in[8];
    const float* fcW  = (const float*)d_in[9];
    const float* fcb  = (const float*)d_in[10];
    float* out = (float*)d_out;

    void *p_xp0, *p_xh, *p_h2, *p_i0h, *p_i0l, *p_r0h, *p_r0l;
    void *p_i1h, *p_i1l, *p_r1h, *p_r1l, *p_fch, *p_fcl;
    cudaGetSymbolAddress(&p_xp0, g_xp0);
    cudaGetSymbolAddress(&p_xh, g_xh);
    cudaGetSymbolAddress(&p_h2, g_h2);
    cudaGetSymbolAddress(&p_i0h, g_Wih0hi); cudaGetSymbolAddress(&p_i0l, g_Wih0lo);
    cudaGetSymbolAddress(&p_r0h, g_Whh0hi); cudaGetSymbolAddress(&p_r0l, g_Whh0lo);
    cudaGetSymbolAddress(&p_i1h, g_Wih1hi); cudaGetSymbolAddress(&p_i1l, g_Wih1lo);
    cudaGetSymbolAddress(&p_r1h, g_Whh1hi); cudaGetSymbolAddress(&p_r1l, g_Whh1lo);
    cudaGetSymbolAddress(&p_fch, g_fcWhi);  cudaGetSymbolAddress(&p_fcl, g_fcWlo);

    static bool attr_done = false;
    if (!attr_done) {
        cudaFuncSetAttribute(gemm_kernel<0>, cudaFuncAttributeMaxDynamicSharedMemorySize, SMEM_DYN);
        cudaFuncSetAttribute(gemm_kernel<2>, cudaFuncAttributeMaxDynamicSharedMemorySize, SMEM_DYN);
        cudaFuncSetAttribute(round_kernel,   cudaFuncAttributeMaxDynamicSharedMemorySize, SMEM_DYN);
        attr_done = true;
    }

    // 1. conversions / splits
    cvt_kernel<<<(BB * TT * II + 255) / 256, 256>>>(x, (hf*)p_xh, BB * TT * II);
    splitw_kernel<<<(HH * II + 255) / 256, 256>>>(Wih0, (hf*)p_i0h, (hf*)p_i0l, HH * II);
    splitw_kernel<<<(HH * HH + 255) / 256, 256>>>(Whh0, (hf*)p_r0h, (hf*)p_r0l, HH * HH);
    splitw_kernel<<<(HH * HH + 255) / 256, 256>>>(Wih1, (hf*)p_i1h, (hf*)p_i1l, HH * HH);
    splitw_kernel<<<(HH * HH + 255) / 256, 256>>>(Whh1, (hf*)p_r1h, (hf*)p_r1l, HH * HH);
    split_pad_fc<<<(HH * HH + 255) / 256, 256>>>(fcW, (hf*)p_fch, (hf*)p_fcl);

    const size_t TH = (size_t)TT * HH;
    const dim3 projGrid(HH / 64, (BB * TT) / 32);   // (16, 1024)
    const dim3 roundGrid(HH / 64, BB / 32, 3);      // (16, 8, 3) = 384 CTAs
    const dim3 fcGrid(HH / 64, BB / 32);            // (16, 8)

    // 2. layer0 bulk input projection: xp0 = x @ Wih0^T + bih0 + bhh0
    gemm_kernel<0><<<projGrid, 256, SMEM_DYN>>>(
        (hf*)p_xh, 0, II, II,
        (hf*)p_i0h, (hf*)p_i0l, bih0, bhh0,
        (float*)p_xp0, 0, HH);

    // 3. pipelined rounds: layer0 step | layer1 proj | layer1 step
    for (int r = 0; r <= TT + 1; r++)
        round_kernel<<<roundGrid, 256, SMEM_DYN>>>(r, bih1, bhh1);

    // 4. FC on h2[:, T-1, :]
    gemm_kernel<2><<<fcGrid, 256, SMEM_DYN>>>(
        (hf*)p_h2, (size_t)(TT - 1) * HH, TH, HH,
        (hf*)p_fch, (hf*)p_fcl, fcb, nullptr,
        out, 0, CC);
}